// round 1
// baseline (speedup 1.0000x reference)
#include <cuda_runtime.h>
#include <cstdint>

#define NXDIM 512
#define NQDIM 128
#define NUDIM 64
#define BROWS 32768

// Scratch (allocation-free rule: __device__ globals)
__device__ float g_baseT[(size_t)NQDIM * BROWS];   // base transposed: [128][B]
__device__ float g_w[(size_t)BROWS * NQDIM];       // w row-major: [B][128]

// ---------------------------------------------------------------------------
// helpers
// ---------------------------------------------------------------------------
__device__ __forceinline__ uint32_t f2tf32(float f) {
    uint32_t r;
    asm("cvt.rna.tf32.f32 %0, %1;" : "=r"(r) : "f"(f));
    return r;
}

__device__ __forceinline__ float tanh_fast(float x) {
    float r;
    asm("tanh.approx.f32 %0, %1;" : "=f"(r) : "f"(x));
    return r;
}

__device__ __forceinline__ void mma_tf32(float c[4], const uint32_t a[4], const uint32_t b[2]) {
    asm volatile(
        "mma.sync.aligned.m16n8k8.row.col.f32.tf32.tf32.f32 "
        "{%0,%1,%2,%3}, {%4,%5,%6,%7}, {%8,%9}, {%0,%1,%2,%3};\n"
        : "+f"(c[0]), "+f"(c[1]), "+f"(c[2]), "+f"(c[3])
        : "r"(a[0]), "r"(a[1]), "r"(a[2]), "r"(a[3]), "r"(b[0]), "r"(b[1]));
}

// ---------------------------------------------------------------------------
// Generic multi-segment GEMM: out[M,N] = sum_s Xs @ Ws^T + bias
//   Xs: [M, Ks] row-major, Ws: [N, Ks] row-major. Ks % 32 == 0.
//   transOut=0: out[m*N + n]; transOut=1: out[n*M + m]
// Block: 128(M) x 128(N) x 32(K), 256 threads (8 warps of 64x32),
// tf32 mma.sync m16n8k8, register-staged global->shared pipeline.
// ---------------------------------------------------------------------------
#define GPAD 36

__global__ void __launch_bounds__(256, 1) gemm_tf32_kernel(
    const float* __restrict__ X0, const float* __restrict__ W0, int K0,
    const float* __restrict__ X1, const float* __restrict__ W1, int K1,
    const float* __restrict__ X2, const float* __restrict__ W2, int K2,
    const float* __restrict__ bias, float* __restrict__ out,
    int N, int M, int transOut)
{
    __shared__ uint32_t sA[128 * GPAD];
    __shared__ uint32_t sB[128 * GPAD];

    const int tid  = threadIdx.x;
    const int bm   = blockIdx.x;
    const int bn   = blockIdx.y;
    const int lane = tid & 31;
    const int warp = tid >> 5;
    const int wm   = warp & 1;    // 0..1 -> 64-row slabs
    const int wn   = warp >> 1;   // 0..3 -> 32-col slabs
    const int qr   = lane >> 2;   // 0..7
    const int qc   = lane & 3;    // 0..3

    const int kt0 = K0 >> 5, kt1 = K1 >> 5, kt2 = K2 >> 5;
    const int ntiles = kt0 + kt1 + kt2;

    float acc[4][4][4];
#pragma unroll
    for (int i = 0; i < 4; i++)
#pragma unroll
        for (int j = 0; j < 4; j++)
#pragma unroll
            for (int k = 0; k < 4; k++) acc[i][j][k] = 0.f;

    float4 ra[4], rb[4];

    // ---- load tile 0 into registers ----
    {
        const float* xp; const float* wp; int ld, off;
        if (0 < kt0)      { xp = X0; wp = W0; ld = K0; off = 0; }
        else if (0 < kt0 + kt1) { xp = X1; wp = W1; ld = K1; off = 0; }
        else              { xp = X2; wp = W2; ld = K2; off = 0; }
#pragma unroll
        for (int i = 0; i < 4; i++) {
            int idx = tid + i * 256;
            int row = idx >> 3;
            int c4  = (idx & 7) << 2;
            ra[i] = *reinterpret_cast<const float4*>(xp + (size_t)(bm * 128 + row) * ld + off + c4);
            rb[i] = *reinterpret_cast<const float4*>(wp + (size_t)(bn * 128 + row) * ld + off + c4);
        }
    }

    for (int t = 0; t < ntiles; t++) {
        // ---- cvt + store staged tile to shared ----
#pragma unroll
        for (int i = 0; i < 4; i++) {
            int idx = tid + i * 256;
            int row = idx >> 3;
            int c4  = (idx & 7) << 2;
            uint32_t* pa = &sA[row * GPAD + c4];
            *reinterpret_cast<uint4*>(pa) =
                make_uint4(f2tf32(ra[i].x), f2tf32(ra[i].y), f2tf32(ra[i].z), f2tf32(ra[i].w));
            uint32_t* pb = &sB[row * GPAD + c4];
            *reinterpret_cast<uint4*>(pb) =
                make_uint4(f2tf32(rb[i].x), f2tf32(rb[i].y), f2tf32(rb[i].z), f2tf32(rb[i].w));
        }
        __syncthreads();

        // ---- prefetch next tile to registers (hides LDG under mma) ----
        if (t + 1 < ntiles) {
            int tn = t + 1;
            const float* xp; const float* wp; int ld, off;
            if (tn < kt0)            { xp = X0; wp = W0; ld = K0; off = tn << 5; }
            else if (tn < kt0 + kt1) { xp = X1; wp = W1; ld = K1; off = (tn - kt0) << 5; }
            else                     { xp = X2; wp = W2; ld = K2; off = (tn - kt0 - kt1) << 5; }
#pragma unroll
            for (int i = 0; i < 4; i++) {
                int idx = tid + i * 256;
                int row = idx >> 3;
                int c4  = (idx & 7) << 2;
                ra[i] = *reinterpret_cast<const float4*>(xp + (size_t)(bm * 128 + row) * ld + off + c4);
                rb[i] = *reinterpret_cast<const float4*>(wp + (size_t)(bn * 128 + row) * ld + off + c4);
            }
        }

        // ---- compute 4 x k8 steps ----
#pragma unroll
        for (int kk = 0; kk < 4; kk++) {
            const int kb = kk * 8;
            uint32_t afr[4][4];
            uint32_t bfr[4][2];
#pragma unroll
            for (int mt = 0; mt < 4; mt++) {
                int r0 = wm * 64 + mt * 16 + qr;
                afr[mt][0] = sA[r0 * GPAD + kb + qc];
                afr[mt][1] = sA[(r0 + 8) * GPAD + kb + qc];
                afr[mt][2] = sA[r0 * GPAD + kb + qc + 4];
                afr[mt][3] = sA[(r0 + 8) * GPAD + kb + qc + 4];
            }
#pragma unroll
            for (int nt = 0; nt < 4; nt++) {
                int n0 = wn * 32 + nt * 8 + qr;
                bfr[nt][0] = sB[n0 * GPAD + kb + qc];
                bfr[nt][1] = sB[n0 * GPAD + kb + qc + 4];
            }
#pragma unroll
            for (int mt = 0; mt < 4; mt++)
#pragma unroll
                for (int nt = 0; nt < 4; nt++)
                    mma_tf32(acc[mt][nt], afr[mt], bfr[nt]);
        }
        __syncthreads();
    }

    // ---- epilogue ----
#pragma unroll
    for (int mt = 0; mt < 4; mt++) {
#pragma unroll
        for (int nt = 0; nt < 4; nt++) {
            int m = bm * 128 + wm * 64 + mt * 16 + qr;
            int n = bn * 128 + wn * 32 + nt * 8 + 2 * qc;
            float b0 = __ldg(bias + n);
            float b1 = __ldg(bias + n + 1);
            float* c = acc[mt][nt];
            if (!transOut) {
                float2 v0 = make_float2(c[0] + b0, c[1] + b1);
                float2 v1 = make_float2(c[2] + b0, c[3] + b1);
                *reinterpret_cast<float2*>(out + (size_t)m * N + n)       = v0;
                *reinterpret_cast<float2*>(out + (size_t)(m + 8) * N + n) = v1;
            } else {
                out[(size_t)n * M + m]           = c[0] + b0;
                out[(size_t)(n + 1) * M + m]     = c[1] + b1;
                out[(size_t)n * M + m + 8]       = c[2] + b0;
                out[(size_t)(n + 1) * M + m + 8] = c[3] + b1;
            }
        }
    }
}

// ---------------------------------------------------------------------------
// Forward substitution: one thread per batch row, w[128] in registers.
//   v_i = baseT[i][r] + sum_{j<i} w_j * D11[i][j];  w_i = tanh(v_i)
// D11 strictly lower triangular. baseT is [128][B] so per-i reads coalesce.
// ---------------------------------------------------------------------------
__global__ void __launch_bounds__(256, 1) subst_kernel(
    const float* __restrict__ baseT, const float* __restrict__ D11,
    float* __restrict__ w_out, int Bn)
{
    const int r = blockIdx.x * 256 + threadIdx.x;

    float w[NQDIM];
#pragma unroll
    for (int i = 0; i < NQDIM; i++) w[i] = 0.f;

#pragma unroll
    for (int i = 0; i < NQDIM; i++) {
        float v0 = __ldg(baseT + (size_t)i * Bn + r);
        float v1 = 0.f, v2 = 0.f, v3 = 0.f;
        const float4* drow = reinterpret_cast<const float4*>(D11 + i * NQDIM);
        const int n4 = (i + 3) >> 2;  // ceil(i/4); constant after unroll
#pragma unroll
        for (int j = 0; j < n4; j++) {
            float4 d = __ldg(drow + j);
            v0 += w[4 * j + 0] * d.x;
            v1 += w[4 * j + 1] * d.y;
            v2 += w[4 * j + 2] * d.z;
            v3 += w[4 * j + 3] * d.w;
        }
        w[i] = tanh_fast((v0 + v1) + (v2 + v3));
    }

    float4* wo = reinterpret_cast<float4*>(w_out + (size_t)r * NQDIM);
#pragma unroll
    for (int j = 0; j < NQDIM / 4; j++)
        wo[j] = make_float4(w[4 * j], w[4 * j + 1], w[4 * j + 2], w[4 * j + 3]);
}

// ---------------------------------------------------------------------------
// launch
// ---------------------------------------------------------------------------
extern "C" void kernel_launch(void* const* d_in, const int* in_sizes, int n_in,
                              void* d_out, int out_size)
{
    const float* xi  = (const float*)d_in[0];
    const float* u   = (const float*)d_in[1];
    const float* A   = (const float*)d_in[2];
    const float* B1  = (const float*)d_in[3];
    const float* B2  = (const float*)d_in[4];
    const float* C1  = (const float*)d_in[5];
    const float* D11 = (const float*)d_in[6];
    const float* D12 = (const float*)d_in[7];
    const float* bx  = (const float*)d_in[8];
    const float* bv  = (const float*)d_in[9];
    float* out = (float*)d_out;

    const int Bn = in_sizes[0] / NXDIM;  // 32768

    void* pBaseT = nullptr;
    void* pW     = nullptr;
    cudaGetSymbolAddress(&pBaseT, g_baseT);
    cudaGetSymbolAddress(&pW, g_w);
    float* baseT = (float*)pBaseT;
    float* w     = (float*)pW;

    dim3 blk(256);

    // base^T = ([xi|u] @ [C1|D12]^T + bv)^T     -> [128, B]
    gemm_tf32_kernel<<<dim3(Bn / 128, 1), blk>>>(
        xi, C1, NXDIM, u, D12, NUDIM, nullptr, nullptr, 0,
        bv, baseT, NQDIM, Bn, 1);

    // forward substitution -> w [B, 128]
    subst_kernel<<<Bn / 256, 256>>>(baseT, D11, w, Bn);

    // out = xi@A^T + w@B1^T + u@B2^T + bx       -> [B, 512]
    gemm_tf32_kernel<<<dim3(Bn / 128, 4), blk>>>(
        xi, A, NXDIM, w, B1, NQDIM, u, B2, NUDIM,
        bx, out, NXDIM, Bn, 0);
}

// round 2
// speedup vs baseline: 1.1564x; 1.1564x over previous
#include <cuda_runtime.h>
#include <cstdint>

#define NXDIM 512
#define NQDIM 128
#define NUDIM 64
#define BROWS 32768

// Scratch (allocation-free rule: __device__ globals)
__device__ float g_baseT[(size_t)NQDIM * BROWS];   // base transposed: [128][B]
__device__ float g_w[(size_t)BROWS * NQDIM];       // w row-major: [B][128]

// ---------------------------------------------------------------------------
// helpers
// ---------------------------------------------------------------------------
__device__ __forceinline__ uint32_t f2tf32(float f) {
    uint32_t r;
    asm("cvt.rna.tf32.f32 %0, %1;" : "=r"(r) : "f"(f));
    return r;
}

__device__ __forceinline__ float tanh_fast(float x) {
    float r;
    asm("tanh.approx.f32 %0, %1;" : "=f"(r) : "f"(x));
    return r;
}

__device__ __forceinline__ void mma_tf32(float c[4], const uint32_t a[4], const uint32_t b[2]) {
    asm volatile(
        "mma.sync.aligned.m16n8k8.row.col.f32.tf32.tf32.f32 "
        "{%0,%1,%2,%3}, {%4,%5,%6,%7}, {%8,%9}, {%0,%1,%2,%3};\n"
        : "+f"(c[0]), "+f"(c[1]), "+f"(c[2]), "+f"(c[3])
        : "r"(a[0]), "r"(a[1]), "r"(a[2]), "r"(a[3]), "r"(b[0]), "r"(b[1]));
}

__device__ __forceinline__ void ldsm_x4(uint32_t r[4], uint32_t addr) {
    asm volatile("ldmatrix.sync.aligned.m8n8.x4.shared.b16 {%0,%1,%2,%3}, [%4];"
                 : "=r"(r[0]), "=r"(r[1]), "=r"(r[2]), "=r"(r[3]) : "r"(addr));
}

// packed f32x2 (Blackwell)
__device__ __forceinline__ uint64_t pack2(float lo, float hi) {
    uint64_t r;
    asm("mov.b64 %0, {%1,%2};" : "=l"(r) : "f"(lo), "f"(hi));
    return r;
}
__device__ __forceinline__ void unpack2(float& lo, float& hi, uint64_t v) {
    asm("mov.b64 {%0,%1}, %2;" : "=f"(lo), "=f"(hi) : "l"(v));
}
__device__ __forceinline__ void ffma2(uint64_t& d, uint64_t a, uint64_t b) {
    asm("fma.rn.f32x2 %0, %1, %2, %0;" : "+l"(d) : "l"(a), "l"(b));
}

// ---------------------------------------------------------------------------
// Generic multi-segment GEMM: out[M,N] = sum_s Xs @ Ws^T + bias
//   Xs: [M, Ks] row-major, Ws: [N, Ks] row-major. Ks % 32 == 0.
//   transOut=0: out[m*N + n]; transOut=1: out[n*M + m]
// Block: 128(M) x 128(N) x 32(K), 256 threads (8 warps of 64x32),
// tf32 mma.sync m16n8k8, LDSM fragment loads, double-buffered smem,
// register-staged global->shared with cvt.rna.tf32.
// ---------------------------------------------------------------------------
#define GPAD 36
// dynamic smem layout (u32 units): A0=0, B0=4608, A1=9216, B1=13824 (each 128*36)
#define GEMM_SMEM_BYTES (4 * 128 * GPAD * 4)

__global__ void __launch_bounds__(256, 1) gemm_tf32_kernel(
    const float* __restrict__ X0, const float* __restrict__ W0, int K0,
    const float* __restrict__ X1, const float* __restrict__ W1, int K1,
    const float* __restrict__ X2, const float* __restrict__ W2, int K2,
    const float* __restrict__ bias, float* __restrict__ out,
    int N, int M, int transOut)
{
    extern __shared__ unsigned char smemraw[];
    uint32_t* sm = reinterpret_cast<uint32_t*>(smemraw);
    const uint32_t sbase = (uint32_t)__cvta_generic_to_shared(smemraw);

    const int tid  = threadIdx.x;
    const int bm   = blockIdx.x;
    const int bn   = blockIdx.y;
    const int lane = tid & 31;
    const int warp = tid >> 5;
    const int wm   = warp & 1;    // 0..1 -> 64-row slabs
    const int wn   = warp >> 1;   // 0..3 -> 32-col slabs
    const int qr   = lane >> 2;   // 0..7
    const int qc   = lane & 3;    // 0..3

    // per-lane LDSM base offsets (bytes)
    const int arow = wm * 64 + (lane & 8) + (lane & 7);
    const int acol = (lane & 16) ? 4 : 0;
    const uint32_t laneA = (uint32_t)((arow * GPAD + acol) * 4);
    const int brow = wn * 32 + ((lane & 16) >> 1) + (lane & 7);
    const int bcol = (lane & 8) ? 4 : 0;
    const uint32_t laneB = (uint32_t)((brow * GPAD + bcol) * 4);

    const int kt0 = K0 >> 5, kt1 = K1 >> 5, kt2 = K2 >> 5;
    const int ntiles = kt0 + kt1 + kt2;

    float acc[4][4][4];
#pragma unroll
    for (int i = 0; i < 4; i++)
#pragma unroll
        for (int j = 0; j < 4; j++)
#pragma unroll
            for (int k = 0; k < 4; k++) acc[i][j][k] = 0.f;

    float4 ra[4], rb[4];

    // ---- load tile 0 into registers ----
    {
        const float* xp; const float* wp_; int ld;
        if (kt0 > 0)      { xp = X0; wp_ = W0; ld = K0; }
        else if (kt1 > 0) { xp = X1; wp_ = W1; ld = K1; }
        else              { xp = X2; wp_ = W2; ld = K2; }
#pragma unroll
        for (int i = 0; i < 4; i++) {
            int idx = tid + i * 256;
            int row = idx >> 3;
            int c4  = (idx & 7) << 2;
            ra[i] = *reinterpret_cast<const float4*>(xp + (size_t)(bm * 128 + row) * ld + c4);
            rb[i] = *reinterpret_cast<const float4*>(wp_ + (size_t)(bn * 128 + row) * ld + c4);
        }
    }
    // ---- cvt + store tile 0 into buffer 0 ----
#pragma unroll
    for (int i = 0; i < 4; i++) {
        int idx = tid + i * 256;
        int row = idx >> 3;
        int c4  = (idx & 7) << 2;
        *reinterpret_cast<uint4*>(sm + row * GPAD + c4) =
            make_uint4(f2tf32(ra[i].x), f2tf32(ra[i].y), f2tf32(ra[i].z), f2tf32(ra[i].w));
        *reinterpret_cast<uint4*>(sm + 4608 + row * GPAD + c4) =
            make_uint4(f2tf32(rb[i].x), f2tf32(rb[i].y), f2tf32(rb[i].z), f2tf32(rb[i].w));
    }
    __syncthreads();

    for (int t = 0; t < ntiles; t++) {
        const int cur = t & 1;

        // ---- prefetch next tile into registers (overlaps mma) ----
        if (t + 1 < ntiles) {
            int tn = t + 1;
            const float* xp; const float* wp_; int ld, off;
            if (tn < kt0)            { xp = X0; wp_ = W0; ld = K0; off = tn << 5; }
            else if (tn < kt0 + kt1) { xp = X1; wp_ = W1; ld = K1; off = (tn - kt0) << 5; }
            else                     { xp = X2; wp_ = W2; ld = K2; off = (tn - kt0 - kt1) << 5; }
#pragma unroll
            for (int i = 0; i < 4; i++) {
                int idx = tid + i * 256;
                int row = idx >> 3;
                int c4  = (idx & 7) << 2;
                ra[i] = *reinterpret_cast<const float4*>(xp + (size_t)(bm * 128 + row) * ld + off + c4);
                rb[i] = *reinterpret_cast<const float4*>(wp_ + (size_t)(bn * 128 + row) * ld + off + c4);
            }
        }

        // ---- compute on buf[cur] ----
        const uint32_t aB = sbase + (cur ? 36864u : 0u);
        const uint32_t bB = sbase + (cur ? 55296u : 18432u);
#pragma unroll
        for (int kk = 0; kk < 4; kk++) {
            uint32_t afr[4][4];
            uint32_t bfr[2][4];
#pragma unroll
            for (int mt = 0; mt < 4; mt++)
                ldsm_x4(afr[mt], aB + laneA + (uint32_t)((mt * 16 * GPAD + kk * 8) * 4));
#pragma unroll
            for (int p = 0; p < 2; p++)
                ldsm_x4(bfr[p], bB + laneB + (uint32_t)((p * 16 * GPAD + kk * 8) * 4));
#pragma unroll
            for (int mt = 0; mt < 4; mt++) {
                mma_tf32(acc[mt][0], afr[mt], &bfr[0][0]);
                mma_tf32(acc[mt][1], afr[mt], &bfr[0][2]);
                mma_tf32(acc[mt][2], afr[mt], &bfr[1][0]);
                mma_tf32(acc[mt][3], afr[mt], &bfr[1][2]);
            }
        }

        // ---- cvt + store next tile into buf[1-cur] ----
        if (t + 1 < ntiles) {
            uint32_t* bufA = sm + (cur ? 0 : 9216);
            uint32_t* bufB = sm + (cur ? 4608 : 13824);
#pragma unroll
            for (int i = 0; i < 4; i++) {
                int idx = tid + i * 256;
                int row = idx >> 3;
                int c4  = (idx & 7) << 2;
                *reinterpret_cast<uint4*>(bufA + row * GPAD + c4) =
                    make_uint4(f2tf32(ra[i].x), f2tf32(ra[i].y), f2tf32(ra[i].z), f2tf32(ra[i].w));
                *reinterpret_cast<uint4*>(bufB + row * GPAD + c4) =
                    make_uint4(f2tf32(rb[i].x), f2tf32(rb[i].y), f2tf32(rb[i].z), f2tf32(rb[i].w));
            }
        }
        __syncthreads();
    }

    // ---- epilogue ----
#pragma unroll
    for (int mt = 0; mt < 4; mt++) {
#pragma unroll
        for (int nt = 0; nt < 4; nt++) {
            int m = bm * 128 + wm * 64 + mt * 16 + qr;
            int n = bn * 128 + wn * 32 + nt * 8 + 2 * qc;
            float b0 = __ldg(bias + n);
            float b1 = __ldg(bias + n + 1);
            float* c = acc[mt][nt];
            if (!transOut) {
                float2 v0 = make_float2(c[0] + b0, c[1] + b1);
                float2 v1 = make_float2(c[2] + b0, c[3] + b1);
                *reinterpret_cast<float2*>(out + (size_t)m * N + n)       = v0;
                *reinterpret_cast<float2*>(out + (size_t)(m + 8) * N + n) = v1;
            } else {
                out[(size_t)n * M + m]           = c[0] + b0;
                out[(size_t)(n + 1) * M + m]     = c[1] + b1;
                out[(size_t)n * M + m + 8]       = c[2] + b0;
                out[(size_t)(n + 1) * M + m + 8] = c[3] + b1;
            }
        }
    }
}

// ---------------------------------------------------------------------------
// Forward substitution: one thread per batch row, w[128] packed in 64 f32x2
// register pairs. D11 staged in 64KB shared (broadcast LDS.128, 2-cyc floor).
//   v_i = baseT[i][r] + sum_{j<i} w_j * D11[i][j];  w_i = tanh(v_i)
// Odd-i half-pair trick is exact: D11[i][i] == 0 and the unset hi lane is 0.0.
// ---------------------------------------------------------------------------
#define SUBST_SMEM_BYTES (NQDIM * NQDIM * 4)

__global__ void __launch_bounds__(256, 1) subst_kernel(
    const float* __restrict__ baseT, const float* __restrict__ D11,
    float* __restrict__ w_out, int Bn)
{
    extern __shared__ unsigned char sraw[];
    float* sD = reinterpret_cast<float*>(sraw);

    // stage D11 into shared
    {
        float4* dst = reinterpret_cast<float4*>(sD);
        const float4* src = reinterpret_cast<const float4*>(D11);
        for (int k = threadIdx.x; k < NQDIM * NQDIM / 4; k += 256)
            dst[k] = src[k];
    }
    __syncthreads();

    const int r = blockIdx.x * 256 + threadIdx.x;

    uint64_t wp[NQDIM / 2];
#pragma unroll
    for (int p = 0; p < NQDIM / 2; p++) wp[p] = 0ull;
    float wlast = 0.f;

#pragma unroll
    for (int i = 0; i < NQDIM; i++) {
        const float bse = __ldg(baseT + (size_t)i * Bn + r);
        uint64_t va = 0ull, vc = 0ull;
        const int np = (i + 1) >> 1;  // pairs covering cols 0..i (diag is 0)
        const ulonglong2* dp = reinterpret_cast<const ulonglong2*>(sD + i * NQDIM);
#pragma unroll
        for (int t = 0; t < (np >> 1); t++) {
            ulonglong2 dd = dp[t];
            ffma2(va, wp[2 * t],     dd.x);
            ffma2(vc, wp[2 * t + 1], dd.y);
        }
        if (np & 1) {
            uint64_t d1 = reinterpret_cast<const unsigned long long*>(dp)[np - 1];
            ffma2(va, wp[np - 1], d1);
        }
        float a0, a1, c0, c1;
        unpack2(a0, a1, va);
        unpack2(c0, c1, vc);
        float wi = tanh_fast(bse + ((a0 + a1) + (c0 + c1)));
        if ((i & 1) == 0) { wp[i >> 1] = pack2(wi, 0.f); wlast = wi; }
        else              { wp[i >> 1] = pack2(wlast, wi); }
    }

    float4* wo = reinterpret_cast<float4*>(w_out + (size_t)r * NQDIM);
#pragma unroll
    for (int p = 0; p < NQDIM / 4; p++) {
        float x0, x1, x2, x3;
        unpack2(x0, x1, wp[2 * p]);
        unpack2(x2, x3, wp[2 * p + 1]);
        wo[p] = make_float4(x0, x1, x2, x3);
    }
}

// ---------------------------------------------------------------------------
// launch
// ---------------------------------------------------------------------------
extern "C" void kernel_launch(void* const* d_in, const int* in_sizes, int n_in,
                              void* d_out, int out_size)
{
    const float* xi  = (const float*)d_in[0];
    const float* u   = (const float*)d_in[1];
    const float* A   = (const float*)d_in[2];
    const float* B1  = (const float*)d_in[3];
    const float* B2  = (const float*)d_in[4];
    const float* C1  = (const float*)d_in[5];
    const float* D11 = (const float*)d_in[6];
    const float* D12 = (const float*)d_in[7];
    const float* bx  = (const float*)d_in[8];
    const float* bv  = (const float*)d_in[9];
    float* out = (float*)d_out;

    const int Bn = in_sizes[0] / NXDIM;  // 32768

    void* pBaseT = nullptr;
    void* pW     = nullptr;
    cudaGetSymbolAddress(&pBaseT, g_baseT);
    cudaGetSymbolAddress(&pW, g_w);
    float* baseT = (float*)pBaseT;
    float* w     = (float*)pW;

    static bool attr_done = false;
    if (!attr_done) {
        cudaFuncSetAttribute(gemm_tf32_kernel,
                             cudaFuncAttributeMaxDynamicSharedMemorySize, GEMM_SMEM_BYTES);
        cudaFuncSetAttribute(subst_kernel,
                             cudaFuncAttributeMaxDynamicSharedMemorySize, SUBST_SMEM_BYTES);
        attr_done = true;
    }

    dim3 blk(256);

    // base^T = ([xi|u] @ [C1|D12]^T + bv)^T     -> [128, B]
    gemm_tf32_kernel<<<dim3(Bn / 128, 1), blk, GEMM_SMEM_BYTES>>>(
        xi, C1, NXDIM, u, D12, NUDIM, nullptr, nullptr, 0,
        bv, baseT, NQDIM, Bn, 1);

    // forward substitution -> w [B, 128]
    subst_kernel<<<Bn / 256, 256, SUBST_SMEM_BYTES>>>(baseT, D11, w, Bn);

    // out = xi@A^T + w@B1^T + u@B2^T + bx       -> [B, 512]
    gemm_tf32_kernel<<<dim3(Bn / 128, 4), blk, GEMM_SMEM_BYTES>>>(
        xi, A, NXDIM, w, B1, NQDIM, u, B2, NUDIM,
        bx, out, NXDIM, Bn, 0);
}